// round 3
// baseline (speedup 1.0000x reference)
#include <cuda_runtime.h>

// MaskedLoss: loss = sum_b sum_{unique (r,c)} (y_true[b,r,c] - y_pred[b,r,c])^2
// B=64, N=1000, K=128. Only K positions of the NxN mask are nonzero
// (duplicates collapse to 1 via set semantics), so this is a sparse gather,
// not a dense reduction. Total useful traffic ~= 2 * B * K * 4B (scattered).

#define MB_B   64
#define MB_K   128
#define MB_N   1000

// Scratch (allocation-free): per-batch partial sums.
__device__ float g_partial[MB_B];

// ---------------------------------------------------------------------------
// Kernel 1: one block per batch row, one thread per index pair.
//   - runtime-detect index width (int64 vs int32) via high-word test
//   - dedup (r*N + c) pairs in shared memory
//   - gather + squared diff + block reduce -> g_partial[b]
// ---------------------------------------------------------------------------
__global__ __launch_bounds__(MB_K)
void masked_loss_partial_kernel(const float* __restrict__ y_true,
                                const float* __restrict__ y_pred,
                                const unsigned int* __restrict__ rows_w,
                                const unsigned int* __restrict__ cols_w)
{
    const int k = threadIdx.x;   // 0..127 : index-pair id
    const int b = blockIdx.x;    // 0..63  : batch row

    __shared__ int   s_idx[MB_K];
    __shared__ float s_red[MB_K / 32];
    __shared__ int   s_is_i32;

    // --- dtype detection ---------------------------------------------------
    // If indices are int64 (values in [0,1000)), every high 32-bit word of the
    // first 64 elements is 0. If they are int32 (128 elements = 512 bytes),
    // those same words are other random indices in [0,1000) and are nonzero
    // with overwhelming probability. Only the first 512 bytes are read, which
    // is in-bounds for either storage width.
    if (k == 0) s_is_i32 = 0;
    __syncthreads();
    if (k < 64) {
        if (rows_w[2 * k + 1] != 0u) s_is_i32 = 1;  // benign write race (all write 1)
    }
    __syncthreads();

    int r, c;
    if (s_is_i32) {
        r = (int)rows_w[k];
        c = (int)cols_w[k];
    } else {
        r = (int)rows_w[2 * k];      // low word of int64
        c = (int)cols_w[2 * k];
    }
    const int my = r * MB_N + c;
    s_idx[k] = my;
    __syncthreads();

    // --- dedup: keep only the FIRST occurrence of each (r,c) ---------------
    bool uniq = true;
    #pragma unroll 4
    for (int j = 0; j < k; ++j) {
        if (s_idx[j] == my) { uniq = false; break; }
    }

    // --- gather + squared diff ---------------------------------------------
    float v = 0.0f;
    if (uniq) {
        const long long off = (long long)b * (long long)(MB_N * MB_N) + (long long)my;
        const float d = y_true[off] - y_pred[off];
        v = d * d;
    }

    // --- block reduce (4 warps) ---------------------------------------------
    #pragma unroll
    for (int o = 16; o > 0; o >>= 1)
        v += __shfl_down_sync(0xffffffffu, v, o);
    if ((k & 31) == 0) s_red[k >> 5] = v;
    __syncthreads();
    if (k == 0)
        g_partial[b] = s_red[0] + s_red[1] + s_red[2] + s_red[3];
}

// ---------------------------------------------------------------------------
// Kernel 2: reduce 64 partials to the scalar output.
// ---------------------------------------------------------------------------
__global__ __launch_bounds__(64)
void masked_loss_final_kernel(float* __restrict__ out)
{
    const int t = threadIdx.x;      // 0..63
    float v = g_partial[t];

    #pragma unroll
    for (int o = 16; o > 0; o >>= 1)
        v += __shfl_down_sync(0xffffffffu, v, o);

    __shared__ float s[2];
    if ((t & 31) == 0) s[t >> 5] = v;
    __syncthreads();
    if (t == 0) out[0] = s[0] + s[1];
}

// ---------------------------------------------------------------------------
// Launch contract
//   d_in[0] = y_true  (float32, B*N*N)
//   d_in[1] = y_pred  (float32, B*N*N)
//   d_in[2] = rows    (int64 or int32, K)
//   d_in[3] = cols    (int64 or int32, K)
//   d_out   = float32 scalar
// ---------------------------------------------------------------------------
extern "C" void kernel_launch(void* const* d_in, const int* in_sizes, int n_in,
                              void* d_out, int out_size)
{
    const float*        y_true = (const float*)d_in[0];
    const float*        y_pred = (const float*)d_in[1];
    const unsigned int* rows_w = (const unsigned int*)d_in[2];
    const unsigned int* cols_w = (const unsigned int*)d_in[3];
    float*              out    = (float*)d_out;

    masked_loss_partial_kernel<<<MB_B, MB_K>>>(y_true, y_pred, rows_w, cols_w);
    masked_loss_final_kernel<<<1, 64>>>(out);
}

// round 4
// speedup vs baseline: 1.4265x; 1.4265x over previous
#include <cuda_runtime.h>

// MaskedLoss: loss = sum_b sum_{unique (r,c)} (y_true[b,r,c] - y_pred[b,r,c])^2
// B=64, N=1000, K=128. Sparse gather: ~8K positions out of 64M elements.
// Single fused kernel: 64 blocks (one per batch), last-block-finishes reduction.

#define MB_B   64
#define MB_K   128
#define MB_N   1000

// Allocation-free scratch. Zero-initialized at module load; the last block
// restores both to 0 every launch, so every graph replay sees the same state.
__device__ float        g_accum;
__device__ unsigned int g_count;

__global__ __launch_bounds__(MB_K)
void masked_loss_fused_kernel(const float* __restrict__ y_true,
                              const float* __restrict__ y_pred,
                              const unsigned int* __restrict__ rows_w,
                              const unsigned int* __restrict__ cols_w,
                              float* __restrict__ out)
{
    const int k = threadIdx.x;   // 0..127 : index-pair id
    const int b = blockIdx.x;    // 0..63  : batch row

    __shared__ int   s_tab[256];     // dedup hash table
    __shared__ float s_red[MB_K / 32];
    __shared__ int   s_is_i32;

    // --- init + dtype detection --------------------------------------------
    // int64 indices (values < 1000) have all-zero high words in the first 64
    // elements; int32 indices make those words other random nonzero indices.
    // Reads only the first 512 bytes — in-bounds for either width.
    s_tab[k]       = -1;
    s_tab[k + 128] = -1;
    if (k == 0) s_is_i32 = 0;
    __syncthreads();
    if (k < 64) {
        if (rows_w[2 * k + 1] != 0u) s_is_i32 = 1;  // benign race: all write 1
    }
    __syncthreads();

    int r, c;
    if (s_is_i32) {
        r = (int)rows_w[k];
        c = (int)cols_w[k];
    } else {
        r = (int)rows_w[2 * k];      // low word of int64
        c = (int)cols_w[2 * k];
    }
    const int my = r * MB_N + c;

    // --- dedup via shared-mem hash (any single winner per value is correct,
    //     since duplicates address the same element) -------------------------
    unsigned int h = ((unsigned int)my * 2654435761u) >> 24;  // 0..255
    bool uniq = false;
    for (;;) {
        int prev = atomicCAS(&s_tab[h], -1, my);
        if (prev == -1) { uniq = true; break; }   // claimed the slot
        if (prev == my) break;                    // duplicate, someone else won
        h = (h + 1) & 255;                        // linear probe
    }

    // --- gather + squared diff ----------------------------------------------
    float v = 0.0f;
    if (uniq) {
        const size_t off = (size_t)b * (size_t)(MB_N * MB_N) + (size_t)my;
        const float d = y_true[off] - y_pred[off];
        v = d * d;
    }

    // --- block reduce (4 warps) ----------------------------------------------
    #pragma unroll
    for (int o = 16; o > 0; o >>= 1)
        v += __shfl_down_sync(0xffffffffu, v, o);
    if ((k & 31) == 0) s_red[k >> 5] = v;
    __syncthreads();

    // --- cross-block reduce: last block to arrive finishes -------------------
    if (k == 0) {
        const float bs = s_red[0] + s_red[1] + s_red[2] + s_red[3];
        atomicAdd(&g_accum, bs);
        __threadfence();                              // order accum before ticket
        const unsigned int t = atomicAdd(&g_count, 1u);
        if (t == MB_B - 1) {                          // I'm the last block
            __threadfence();                          // acquire: see all accum adds
            const float total = atomicExch(&g_accum, 0.0f);  // read + reset
            g_count = 0;                              // reset for next replay
            out[0] = total;
        }
    }
}

// ---------------------------------------------------------------------------
// Launch contract
//   d_in[0] = y_true  (float32, B*N*N)
//   d_in[1] = y_pred  (float32, B*N*N)
//   d_in[2] = rows    (int64 or int32, K)
//   d_in[3] = cols    (int64 or int32, K)
//   d_out   = float32 scalar
// ---------------------------------------------------------------------------
extern "C" void kernel_launch(void* const* d_in, const int* in_sizes, int n_in,
                              void* d_out, int out_size)
{
    const float*        y_true = (const float*)d_in[0];
    const float*        y_pred = (const float*)d_in[1];
    const unsigned int* rows_w = (const unsigned int*)d_in[2];
    const unsigned int* cols_w = (const unsigned int*)d_in[3];
    float*              out    = (float*)d_out;

    masked_loss_fused_kernel<<<MB_B, MB_K>>>(y_true, y_pred, rows_w, cols_w, out);
}